// round 9
// baseline (speedup 1.0000x reference)
#include <cuda_runtime.h>
#include <math.h>

#define EPSV 1e-4f

// scratch (device globals; allocation is banned)
__device__ __align__(16) float g_B[25165824];       // 12*512 matrices of 64x64
__device__ __align__(16) float g_Vt[25165824];      // eigenvectors, COLUMN-major V[col*64+row]
__device__ __align__(16) float g_w[393216];         // eigenvalues
__device__ __align__(16) float g_state[10485760];   // 5*512*4096
__device__ __align__(16) float g_Lstate[10485760];  // logm(states)

// ---------------- bimap: Y = W X W^T (64x64) --------------------------------
__device__ __forceinline__ void bimap64(const float* __restrict__ X,
                                        const float* __restrict__ W,
                                        float* __restrict__ Y,
                                        float* Ws, float* Xs) {
  const int t = threadIdx.x;
  for (int i = t; i < 4096; i += 256) {
    int r = i >> 6, c = i & 63;
    Ws[r * 65 + c] = W[i];
    Xs[r * 65 + c] = X[i];
  }
  __syncthreads();
  const int i0 = (t >> 4) * 4, j0 = (t & 15) * 4;
  float acc[4][4] = {};
  for (int k = 0; k < 64; k++) {          // T = W * X
    float a[4], b[4];
#pragma unroll
    for (int r = 0; r < 4; r++) a[r] = Ws[(i0 + r) * 65 + k];
#pragma unroll
    for (int c = 0; c < 4; c++) b[c] = Xs[k * 65 + j0 + c];
#pragma unroll
    for (int r = 0; r < 4; r++)
#pragma unroll
      for (int c = 0; c < 4; c++) acc[r][c] += a[r] * b[c];
  }
  __syncthreads();
#pragma unroll
  for (int r = 0; r < 4; r++)
#pragma unroll
    for (int c = 0; c < 4; c++) Xs[(i0 + r) * 65 + j0 + c] = acc[r][c];
  __syncthreads();
  float acc2[4][4] = {};
  for (int k = 0; k < 64; k++) {          // Y = T * W^T
    float a[4], b[4];
#pragma unroll
    for (int r = 0; r < 4; r++) a[r] = Xs[(i0 + r) * 65 + k];
#pragma unroll
    for (int c = 0; c < 4; c++) b[c] = Ws[(j0 + c) * 65 + k];
#pragma unroll
    for (int r = 0; r < 4; r++)
#pragma unroll
      for (int c = 0; c < 4; c++) acc2[r][c] += a[r] * b[c];
  }
#pragma unroll
  for (int r = 0; r < 4; r++)
#pragma unroll
    for (int c = 0; c < 4; c++) Y[(i0 + r) * 64 + j0 + c] = acc2[r][c];
}

__global__ void k_bimap_pre(const float* __restrict__ s0, const float* __restrict__ s1,
                            const float* __restrict__ Wp0, const float* __restrict__ Wp1) {
  __shared__ float Ws[4160], Xs[4160];
  int m = blockIdx.x, slot = m >> 9, bc = m & 511;
  const float* X = (slot ? s1 : s0) + (size_t)bc * 4096;
  const float* W = slot ? Wp1 : Wp0;
  bimap64(X, W, g_B + (size_t)m * 4096, Ws, Xs);
}

__global__ void k_bimap_step(const float* __restrict__ Wop, int o) {
  __shared__ float Ws[4160], Xs[4160];
  int m = blockIdx.x;
  int j = m / 1536, rem = m % 1536, r = rem / 512, k = r + 1, bc = rem % 512;
  const float* X = g_state + (size_t)(j * 512 + bc) * 4096;
  const float* W = Wop + (size_t)((o + j) * 4 + k) * 4096;
  bimap64(X, W, g_B + (size_t)m * 4096, Ws, Xs);
}

// ---------------- batched Jacobi eigh: ping-pong, 1 barrier/round ------------
// A stored pitch-64 with row-rotation swizzle col' = (c + d(r)) & 63,
// d(r) = r<32 ? r : 63-r  -> bank (c+d(r))%32 conflict-free on all XOR-pair row sets.
__global__ void __launch_bounds__(256, 4) k_eigh(int useL, int off) {
  __shared__ float As[8192];   // two 4096-float buffers (ping-pong)
  __shared__ float Vt[4096];   // V column-major: Vt[col*64+row]
  const int t = threadIdx.x;
  const int lane = t & 31, wid = t >> 5;
  const int m = blockIdx.x;
  const float* src = (useL ? g_Lstate : g_B) + (size_t)(off + m) * 4096;

  float loc = 0.f;
  for (int i = t; i < 4096; i += 256) {
    int r = i >> 6, c = i & 63;
    float v = 0.5f * (src[i] + src[c * 64 + r]);
    int d = (r < 32) ? r : 63 - r;
    As[(r << 6) + ((c + d) & 63)] = v;
    Vt[i] = (r == c) ? 1.f : 0.f;
    loc += v * v;
  }
#pragma unroll
  for (int o2 = 16; o2; o2 >>= 1) loc += __shfl_xor_sync(~0u, loc, o2);
  if (lane == 0) As[4096 + wid] = loc;   // buffer1 scratch (overwritten in round 0)
  __syncthreads();
  float snrm2 = 0.f;
#pragma unroll
  for (int i = 0; i < 8; i++) snrm2 += As[4096 + i];
  const float thr = snrm2 * 1e-12f;      // per-thread threshold (sum <= 256*thr)

  int cur = 0;
  for (int sweep = 0; sweep < 18; sweep++) {
    // per-thread off-diagonal partial over own strided elements (self-written or
    // made visible by the round-end barrier)
    float l2 = 0.f;
    const int base = cur << 12;
    for (int i = t; i < 4096; i += 256) {
      int r = i >> 6, c = i & 63;
      int d = (r < 32) ? r : 63 - r;
      float v = As[base + (r << 6) + ((c + d) & 63)];
      l2 += (r != c) ? v * v : 0.f;
    }
    if (__syncthreads_count(l2 > thr) == 0) break;

    for (int mr = 1; mr < 64; mr++) {
      const int h = 31 - __clz(mr);
      const int msk = (1 << h) - 1;
      const int pi = ((lane >> h) << (h + 1)) | (lane & msk);
      const int qi = pi ^ mr;
      const int dpi = (pi < 32) ? pi : 63 - pi;
      const int dqi = (qi < 32) ? qi : 63 - qi;
      const int cb = cur << 12;
      const int bp = cb + (pi << 6), bq = cb + (qi << 6);
      float app = As[bp + ((pi + dpi) & 63)];
      float aqq = As[bq + ((qi + dqi) & 63)];
      float apq = As[bp + ((qi + dpi) & 63)];
      float cc = 1.f, ss = 0.f;
      if (fabsf(apq) > 1e-37f) {
        float tau = (aqq - app) / (2.f * apq);
        float tt = copysignf(1.f, tau) / (fabsf(tau) + sqrtf(1.f + tau * tau));
        cc = rsqrtf(1.f + tt * tt);
        ss = tt * cc;
      }
      const int nb = (cb ^ 4096);
      const int nbp = nb + (pi << 6), nbq = nb + (qi << 6);
#pragma unroll
      for (int k = 0; k < 4; k++) {
        const int j = wid + 8 * k;
        const float cj = __shfl_sync(~0u, cc, j);
        const float sj = __shfl_sync(~0u, ss, j);
        const int pj = ((j >> h) << (h + 1)) | (j & msk);
        const int qj = pj ^ mr;
        const int cpp = (pj + dpi) & 63, cqp = (qj + dpi) & 63;
        const int cpq = (pj + dqi) & 63, cqq = (qj + dqi) & 63;

        float b00 = As[bp + cpp], b01 = As[bp + cqp];
        float b10 = As[bq + cpq], b11 = As[bq + cqq];
        float t00 = cc * b00 - ss * b10, t01 = cc * b01 - ss * b11;
        float t10 = ss * b00 + cc * b10, t11 = ss * b01 + cc * b11;
        As[nbp + cpp] = t00 * cj - t01 * sj;
        As[nbp + cqp] = t00 * sj + t01 * cj;
        As[nbq + cpq] = t10 * cj - t11 * sj;
        As[nbq + cqq] = t10 * sj + t11 * cj;

        const int vp = pj << 6, vq = qj << 6;
        float vp0 = Vt[vp + lane], vq0 = Vt[vq + lane];
        Vt[vp + lane] = cj * vp0 - sj * vq0;
        Vt[vq + lane] = sj * vp0 + cj * vq0;
        float vp1 = Vt[vp + 32 + lane], vq1 = Vt[vq + 32 + lane];
        Vt[vp + 32 + lane] = cj * vp1 - sj * vq1;
        Vt[vq + 32 + lane] = sj * vp1 + cj * vq1;
      }
      __syncthreads();
      cur ^= 1;
    }
  }
  if (t < 64) {
    int d = (t < 32) ? t : 63 - t;
    g_w[(size_t)m * 64 + t] = As[(cur << 12) + (t << 6) + ((t + d) & 63)];
  }
  for (int i = t; i < 4096; i += 256)
    g_Vt[(size_t)m * 4096 + i] = Vt[i];   // column-major out
}

// transpose-on-load of column-major g_Vt into row-major pitch-65 smem
__device__ __forceinline__ void loadV(const float* __restrict__ V, float* Vs, int t) {
  for (int i = t; i < 4096; i += 256) Vs[(i & 63) * 65 + (i >> 6)] = V[i];
}

// ---------------- reconstructions V f(w) V^T --------------------------------
__global__ void k_recon_pre() {  // state = V clip(w) V^T ; Lstate = V log(clip(w)) V^T
  __shared__ float Vs[4160], fc[64], fl[64];
  const int m = blockIdx.x, t = threadIdx.x;
  const int slot = m >> 9, bc = m & 511;
  loadV(g_Vt + (size_t)m * 4096, Vs, t);
  if (t < 64) {
    float cw = fmaxf(g_w[(size_t)m * 64 + t], EPSV);
    fc[t] = cw; fl[t] = logf(cw);
  }
  __syncthreads();
  const int i0 = (t >> 4) * 4, j0 = (t & 15) * 4;
  float a[4][4] = {}, b[4][4] = {};
  for (int k = 0; k < 64; k++) {
    float u[4], v[4];
#pragma unroll
    for (int r = 0; r < 4; r++) u[r] = Vs[(i0 + r) * 65 + k];
#pragma unroll
    for (int c = 0; c < 4; c++) v[c] = Vs[(j0 + c) * 65 + k];
    float fck = fc[k], flk = fl[k];
#pragma unroll
    for (int r = 0; r < 4; r++)
#pragma unroll
      for (int c = 0; c < 4; c++) {
        float p = u[r] * v[c];
        a[r][c] += p * fck;
        b[r][c] += p * flk;
      }
  }
  float* st = g_state + (size_t)(slot * 512 + bc) * 4096;
  float* ls = g_Lstate + (size_t)(slot * 512 + bc) * 4096;
#pragma unroll
  for (int r = 0; r < 4; r++)
#pragma unroll
    for (int c = 0; c < 4; c++) {
      st[(i0 + r) * 64 + j0 + c] = a[r][c];
      ls[(i0 + r) * 64 + j0 + c] = b[r][c];
    }
}

__global__ void k_recon_log() {  // g_B[m] = V log(clip(w)) V^T
  __shared__ float Vs[4160], fl[64];
  const int m = blockIdx.x, t = threadIdx.x;
  loadV(g_Vt + (size_t)m * 4096, Vs, t);
  if (t < 64) fl[t] = logf(fmaxf(g_w[(size_t)m * 64 + t], EPSV));
  __syncthreads();
  const int i0 = (t >> 4) * 4, j0 = (t & 15) * 4;
  float a[4][4] = {};
  for (int k = 0; k < 64; k++) {
    float u[4], v[4];
#pragma unroll
    for (int r = 0; r < 4; r++) u[r] = Vs[(i0 + r) * 65 + k];
#pragma unroll
    for (int c = 0; c < 4; c++) v[c] = Vs[(j0 + c) * 65 + k] * fl[k];
#pragma unroll
    for (int r = 0; r < 4; r++)
#pragma unroll
      for (int c = 0; c < 4; c++) a[r][c] += u[r] * v[c];
  }
  float* dst = g_B + (size_t)m * 4096;
#pragma unroll
  for (int r = 0; r < 4; r++)
#pragma unroll
    for (int c = 0; c < 4; c++) dst[(i0 + r) * 64 + j0 + c] = a[r][c];
}

__global__ void k_recon_exp(int ns, float* __restrict__ out) {  // state = V exp(w) V^T
  __shared__ float Vs[4160], fe[64];
  const int m = blockIdx.x, t = threadIdx.x;
  loadV(g_Vt + (size_t)m * 4096, Vs, t);
  if (t < 64) fe[t] = expf(g_w[(size_t)m * 64 + t]);
  __syncthreads();
  const int i0 = (t >> 4) * 4, j0 = (t & 15) * 4;
  float a[4][4] = {};
  for (int k = 0; k < 64; k++) {
    float u[4], v[4];
#pragma unroll
    for (int r = 0; r < 4; r++) u[r] = Vs[(i0 + r) * 65 + k];
#pragma unroll
    for (int c = 0; c < 4; c++) v[c] = Vs[(j0 + c) * 65 + k] * fe[k];
#pragma unroll
    for (int r = 0; r < 4; r++)
#pragma unroll
      for (int c = 0; c < 4; c++) a[r][c] += u[r] * v[c];
  }
  float* st = g_state + (size_t)(ns * 512 + m) * 4096;
  int b = m >> 4, c0 = m & 15;
  float* od = out + (size_t)((b * 48 + (ns - 2) * 16 + c0)) * 4096;
#pragma unroll
  for (int r = 0; r < 4; r++)
#pragma unroll
    for (int c = 0; c < 4; c++) {
      float v = a[r][c];
      st[(i0 + r) * 64 + j0 + c] = v;
      od[(i0 + r) * 64 + j0 + c] = v;
    }
}

// ---------------- mean of weighted logs --------------------------------------
__global__ void k_mean(const float* __restrict__ wts, int o, int J, int ns) {
  const int bc = blockIdx.x, t = threadIdx.x;
  float wl[4][4];
  for (int j = 0; j < J; j++)
    for (int k = 0; k < 4; k++) wl[j][k] = wts[(o + j) * 4 + k];
  const float inv = 1.f / (float)J;
  float* dst = g_Lstate + (size_t)(ns * 512 + bc) * 4096;
  for (int e = t; e < 4096; e += 256) {
    float acc = 0.f;
    for (int j = 0; j < J; j++) {
      acc += wl[j][0] * g_Lstate[(size_t)(j * 512 + bc) * 4096 + e];
      for (int r = 0; r < 3; r++)
        acc += wl[j][r + 1] * g_B[(size_t)((j * 3 + r) * 512 + bc) * 4096 + e];
    }
    dst[e] = acc * inv;
  }
}

// ---------------- host ---------------------------------------------------------
extern "C" void kernel_launch(void* const* d_in, const int* in_sizes, int n_in,
                              void* d_out, int out_size) {
  const float* s0  = (const float*)d_in[0];
  const float* s1  = (const float*)d_in[1];
  const float* wts = (const float*)d_in[2];
  const float* Wp0 = (const float*)d_in[3];
  const float* Wp1 = (const float*)d_in[4];
  const float* Wop = (const float*)d_in[5];
  float* out = (float*)d_out;
  (void)in_sizes; (void)n_in; (void)out_size;

  // preprocess: reig(bimap(s_i, Wp_i)) + cached log
  k_bimap_pre<<<1024, 256>>>(s0, s1, Wp0, Wp1);
  k_eigh<<<1024, 256>>>(0, 0);
  k_recon_pre<<<1024, 256>>>();

  const int offs[3] = {0, 2, 5};
  for (int s = 0; s < 3; s++) {
    int J = 2 + s, o = offs[s], ns = 2 + s;
    int nb = J * 3 * 512;
    k_bimap_step<<<nb, 256>>>(Wop, o);
    k_eigh<<<nb, 256>>>(0, 0);
    k_recon_log<<<nb, 256>>>();
    k_mean<<<512, 256>>>(wts, o, J, ns);
    k_eigh<<<512, 256>>>(1, ns * 512);
    k_recon_exp<<<512, 256>>>(ns, out);
  }
}

// round 10
// speedup vs baseline: 1.0579x; 1.0579x over previous
#include <cuda_runtime.h>
#include <math.h>

#define EPSV 1e-4f

// scratch (device globals; allocation is banned)
__device__ __align__(16) float g_B[25165824];       // 12*512 matrices of 64x64
__device__ __align__(16) float g_Vt[25165824];      // eigenvectors (cols = eigvecs)
__device__ __align__(16) float g_w[393216];         // eigenvalues
__device__ __align__(16) float g_state[10485760];   // 5*512*4096
__device__ __align__(16) float g_Lstate[10485760];  // logm(states)

// A swizzle: element (r,c) at r*65 + ((c + d(r)) & 63),
// d(r) = r<32 ? 0 : (63-2r) mod 64  ->  bank = (f(r)+c) mod 32, f injective on
// every XOR pair-set => conflict-free phase-b A traffic in all 63 rounds.
__device__ __forceinline__ int drow(int r) { return (r < 32) ? 0 : ((63 - 2 * r) & 63); }

// ---------------- bimap: Y = W X W^T (64x64) --------------------------------
__device__ __forceinline__ void bimap64(const float* __restrict__ X,
                                        const float* __restrict__ W,
                                        float* __restrict__ Y,
                                        float* Ws, float* Xs) {
  const int t = threadIdx.x;
  for (int i = t; i < 4096; i += 256) {
    int r = i >> 6, c = i & 63;
    Ws[r * 65 + c] = W[i];
    Xs[r * 65 + c] = X[i];
  }
  __syncthreads();
  const int i0 = (t >> 4) * 4, j0 = (t & 15) * 4;
  float acc[4][4] = {};
  for (int k = 0; k < 64; k++) {          // T = W * X
    float a[4], b[4];
#pragma unroll
    for (int r = 0; r < 4; r++) a[r] = Ws[(i0 + r) * 65 + k];
#pragma unroll
    for (int c = 0; c < 4; c++) b[c] = Xs[k * 65 + j0 + c];
#pragma unroll
    for (int r = 0; r < 4; r++)
#pragma unroll
      for (int c = 0; c < 4; c++) acc[r][c] += a[r] * b[c];
  }
  __syncthreads();
#pragma unroll
  for (int r = 0; r < 4; r++)
#pragma unroll
    for (int c = 0; c < 4; c++) Xs[(i0 + r) * 65 + j0 + c] = acc[r][c];
  __syncthreads();
  float acc2[4][4] = {};
  for (int k = 0; k < 64; k++) {          // Y = T * W^T
    float a[4], b[4];
#pragma unroll
    for (int r = 0; r < 4; r++) a[r] = Xs[(i0 + r) * 65 + k];
#pragma unroll
    for (int c = 0; c < 4; c++) b[c] = Ws[(j0 + c) * 65 + k];
#pragma unroll
    for (int r = 0; r < 4; r++)
#pragma unroll
      for (int c = 0; c < 4; c++) acc2[r][c] += a[r] * b[c];
  }
#pragma unroll
  for (int r = 0; r < 4; r++)
#pragma unroll
    for (int c = 0; c < 4; c++) Y[(i0 + r) * 64 + j0 + c] = acc2[r][c];
}

__global__ void k_bimap_pre(const float* __restrict__ s0, const float* __restrict__ s1,
                            const float* __restrict__ Wp0, const float* __restrict__ Wp1) {
  __shared__ float Ws[4160], Xs[4160];
  int m = blockIdx.x, slot = m >> 9, bc = m & 511;
  const float* X = (slot ? s1 : s0) + (size_t)bc * 4096;
  const float* W = slot ? Wp1 : Wp0;
  bimap64(X, W, g_B + (size_t)m * 4096, Ws, Xs);
}

__global__ void k_bimap_step(const float* __restrict__ Wop, int o) {
  __shared__ float Ws[4160], Xs[4160];
  int m = blockIdx.x;
  int j = m / 1536, rem = m % 1536, r = rem / 512, k = r + 1, bc = rem % 512;
  const float* X = g_state + (size_t)(j * 512 + bc) * 4096;
  const float* W = Wop + (size_t)((o + j) * 4 + k) * 4096;
  bimap64(X, W, g_B + (size_t)m * 4096, Ws, Xs);
}

// ---------------- batched Jacobi eigh: fused 2x2 rounds, swizzled A ----------
__global__ void __launch_bounds__(256, 4) k_eigh(int useL, int off) {
  __shared__ float As[4160], Vs[4160];
  __shared__ float red[8];
  __shared__ float snrm2;
  __shared__ int sdone;
  const int t = threadIdx.x;
  const int lane = t & 31, wid = t >> 5;
  const int m = blockIdx.x;
  const float* src = (useL ? g_Lstate : g_B) + (size_t)(off + m) * 4096;

  float loc = 0.f;
  for (int i = t; i < 4096; i += 256) {
    int r = i >> 6, c = i & 63;
    float v = 0.5f * (src[i] + src[c * 64 + r]);
    As[r * 65 + ((c + drow(r)) & 63)] = v;
    Vs[r * 65 + c] = (r == c) ? 1.f : 0.f;
    loc += v * v;
  }
#pragma unroll
  for (int o2 = 16; o2; o2 >>= 1) loc += __shfl_xor_sync(~0u, loc, o2);
  if (lane == 0) red[wid] = loc;
  __syncthreads();
  if (t == 0) {
    float s = 0.f;
    for (int i = 0; i < 8; i++) s += red[i];
    snrm2 = s;
  }
  __syncthreads();

  for (int sweep = 0; sweep < 18; sweep++) {
    // convergence check: off-diagonal Frobenius^2
    float l2 = 0.f;
    for (int i = t; i < 4096; i += 256) {
      int r = i >> 6, c = i & 63;
      float v = As[r * 65 + ((c + drow(r)) & 63)];
      l2 += (r != c) ? v * v : 0.f;
    }
#pragma unroll
    for (int o2 = 16; o2; o2 >>= 1) l2 += __shfl_xor_sync(~0u, l2, o2);
    if (lane == 0) red[wid] = l2;
    __syncthreads();
    if (t == 0) {
      float s = 0.f;
      for (int i = 0; i < 8; i++) s += red[i];
      sdone = (s <= 1e-11f * snrm2) ? 1 : 0;
    }
    __syncthreads();
    if (sdone) break;

    for (int mr = 1; mr < 64; mr++) {
      const int h = 31 - __clz(mr);
      const int msk = (1 << h) - 1;
      // phase a: every warp computes all 32 rotations (lane = pair index)
      const int pi = ((lane >> h) << (h + 1)) | (lane & msk);
      const int qi = pi ^ mr;
      const int dpi = drow(pi), dqi = drow(qi);
      const int bp = pi * 65, bq = qi * 65;
      float app = As[bp + ((pi + dpi) & 63)];
      float aqq = As[bq + ((qi + dqi) & 63)];
      float apq = As[bp + ((qi + dpi) & 63)];
      float cc = 1.f, ss = 0.f;
      if (fabsf(apq) > 1e-37f) {
        float tau = (aqq - app) / (2.f * apq);
        float tt = copysignf(1.f, tau) / (fabsf(tau) + sqrtf(1.f + tau * tau));
        cc = rsqrtf(1.f + tt * tt);
        ss = tt * cc;
      }
      __syncthreads();  // rotation reads done before block writes

      // phase b: fused two-sided update. Thread (wid,lane) owns A blocks
      // (i=lane, j=wid+8k) and V col-pairs j at rows lane, lane+32.
#pragma unroll
      for (int k = 0; k < 4; k++) {
        const int j = wid + 8 * k;
        const float cj = __shfl_sync(~0u, cc, j);
        const float sj = __shfl_sync(~0u, ss, j);
        const int pj = ((j >> h) << (h + 1)) | (j & msk);
        const int qj = pj ^ mr;

        const int a00 = bp + ((pj + dpi) & 63), a01 = bp + ((qj + dpi) & 63);
        const int a10 = bq + ((pj + dqi) & 63), a11 = bq + ((qj + dqi) & 63);
        float b00 = As[a00], b01 = As[a01];
        float b10 = As[a10], b11 = As[a11];
        float t00 = cc * b00 - ss * b10, t01 = cc * b01 - ss * b11;
        float t10 = ss * b00 + cc * b10, t11 = ss * b01 + cc * b11;
        As[a00] = t00 * cj - t01 * sj;
        As[a01] = t00 * sj + t01 * cj;
        As[a10] = t10 * cj - t11 * sj;
        As[a11] = t10 * sj + t11 * cj;

        float vp0 = Vs[lane * 65 + pj], vq0 = Vs[lane * 65 + qj];
        Vs[lane * 65 + pj] = cj * vp0 - sj * vq0;
        Vs[lane * 65 + qj] = sj * vp0 + cj * vq0;
        float vp1 = Vs[(lane + 32) * 65 + pj], vq1 = Vs[(lane + 32) * 65 + qj];
        Vs[(lane + 32) * 65 + pj] = cj * vp1 - sj * vq1;
        Vs[(lane + 32) * 65 + qj] = sj * vp1 + cj * vq1;
      }
      __syncthreads();
    }
  }
  if (t < 64) g_w[(size_t)m * 64 + t] = As[t * 65 + ((t + drow(t)) & 63)];
  for (int i = t; i < 4096; i += 256)
    g_Vt[(size_t)m * 4096 + i] = Vs[(i >> 6) * 65 + (i & 63)];
}

// ---------------- reconstructions V f(w) V^T --------------------------------
__global__ void k_recon_pre() {  // state = V clip(w) V^T ; Lstate = V log(clip(w)) V^T
  __shared__ float Vs[4160], fc[64], fl[64];
  const int m = blockIdx.x, t = threadIdx.x;
  const int slot = m >> 9, bc = m & 511;
  const float* V = g_Vt + (size_t)m * 4096;
  for (int i = t; i < 4096; i += 256) Vs[(i >> 6) * 65 + (i & 63)] = V[i];
  if (t < 64) {
    float cw = fmaxf(g_w[(size_t)m * 64 + t], EPSV);
    fc[t] = cw; fl[t] = logf(cw);
  }
  __syncthreads();
  const int i0 = (t >> 4) * 4, j0 = (t & 15) * 4;
  float a[4][4] = {}, b[4][4] = {};
  for (int k = 0; k < 64; k++) {
    float u[4], v[4];
#pragma unroll
    for (int r = 0; r < 4; r++) u[r] = Vs[(i0 + r) * 65 + k];
#pragma unroll
    for (int c = 0; c < 4; c++) v[c] = Vs[(j0 + c) * 65 + k];
    float fck = fc[k], flk = fl[k];
#pragma unroll
    for (int r = 0; r < 4; r++)
#pragma unroll
      for (int c = 0; c < 4; c++) {
        float p = u[r] * v[c];
        a[r][c] += p * fck;
        b[r][c] += p * flk;
      }
  }
  float* st = g_state + (size_t)(slot * 512 + bc) * 4096;
  float* ls = g_Lstate + (size_t)(slot * 512 + bc) * 4096;
#pragma unroll
  for (int r = 0; r < 4; r++)
#pragma unroll
    for (int c = 0; c < 4; c++) {
      st[(i0 + r) * 64 + j0 + c] = a[r][c];
      ls[(i0 + r) * 64 + j0 + c] = b[r][c];
    }
}

__global__ void k_recon_log() {  // g_B[m] = V log(clip(w)) V^T
  __shared__ float Vs[4160], fl[64];
  const int m = blockIdx.x, t = threadIdx.x;
  const float* V = g_Vt + (size_t)m * 4096;
  for (int i = t; i < 4096; i += 256) Vs[(i >> 6) * 65 + (i & 63)] = V[i];
  if (t < 64) fl[t] = logf(fmaxf(g_w[(size_t)m * 64 + t], EPSV));
  __syncthreads();
  const int i0 = (t >> 4) * 4, j0 = (t & 15) * 4;
  float a[4][4] = {};
  for (int k = 0; k < 64; k++) {
    float u[4], v[4];
#pragma unroll
    for (int r = 0; r < 4; r++) u[r] = Vs[(i0 + r) * 65 + k];
#pragma unroll
    for (int c = 0; c < 4; c++) v[c] = Vs[(j0 + c) * 65 + k] * fl[k];
#pragma unroll
    for (int r = 0; r < 4; r++)
#pragma unroll
      for (int c = 0; c < 4; c++) a[r][c] += u[r] * v[c];
  }
  float* dst = g_B + (size_t)m * 4096;
#pragma unroll
  for (int r = 0; r < 4; r++)
#pragma unroll
    for (int c = 0; c < 4; c++) dst[(i0 + r) * 64 + j0 + c] = a[r][c];
}

__global__ void k_recon_exp(int ns, float* __restrict__ out) {  // state = V exp(w) V^T
  __shared__ float Vs[4160], fe[64];
  const int m = blockIdx.x, t = threadIdx.x;
  const float* V = g_Vt + (size_t)m * 4096;
  for (int i = t; i < 4096; i += 256) Vs[(i >> 6) * 65 + (i & 63)] = V[i];
  if (t < 64) fe[t] = expf(g_w[(size_t)m * 64 + t]);
  __syncthreads();
  const int i0 = (t >> 4) * 4, j0 = (t & 15) * 4;
  float a[4][4] = {};
  for (int k = 0; k < 64; k++) {
    float u[4], v[4];
#pragma unroll
    for (int r = 0; r < 4; r++) u[r] = Vs[(i0 + r) * 65 + k];
#pragma unroll
    for (int c = 0; c < 4; c++) v[c] = Vs[(j0 + c) * 65 + k] * fe[k];
#pragma unroll
    for (int r = 0; r < 4; r++)
#pragma unroll
      for (int c = 0; c < 4; c++) a[r][c] += u[r] * v[c];
  }
  float* st = g_state + (size_t)(ns * 512 + m) * 4096;
  int b = m >> 4, c0 = m & 15;
  float* od = out + (size_t)((b * 48 + (ns - 2) * 16 + c0)) * 4096;
#pragma unroll
  for (int r = 0; r < 4; r++)
#pragma unroll
    for (int c = 0; c < 4; c++) {
      float v = a[r][c];
      st[(i0 + r) * 64 + j0 + c] = v;
      od[(i0 + r) * 64 + j0 + c] = v;
    }
}

// ---------------- mean of weighted logs --------------------------------------
__global__ void k_mean(const float* __restrict__ wts, int o, int J, int ns) {
  const int bc = blockIdx.x, t = threadIdx.x;
  float wl[4][4];
  for (int j = 0; j < J; j++)
    for (int k = 0; k < 4; k++) wl[j][k] = wts[(o + j) * 4 + k];
  const float inv = 1.f / (float)J;
  float* dst = g_Lstate + (size_t)(ns * 512 + bc) * 4096;
  for (int e = t; e < 4096; e += 256) {
    float acc = 0.f;
    for (int j = 0; j < J; j++) {
      acc += wl[j][0] * g_Lstate[(size_t)(j * 512 + bc) * 4096 + e];
      for (int r = 0; r < 3; r++)
        acc += wl[j][r + 1] * g_B[(size_t)((j * 3 + r) * 512 + bc) * 4096 + e];
    }
    dst[e] = acc * inv;
  }
}

// ---------------- host ---------------------------------------------------------
extern "C" void kernel_launch(void* const* d_in, const int* in_sizes, int n_in,
                              void* d_out, int out_size) {
  const float* s0  = (const float*)d_in[0];
  const float* s1  = (const float*)d_in[1];
  const float* wts = (const float*)d_in[2];
  const float* Wp0 = (const float*)d_in[3];
  const float* Wp1 = (const float*)d_in[4];
  const float* Wop = (const float*)d_in[5];
  float* out = (float*)d_out;
  (void)in_sizes; (void)n_in; (void)out_size;

  // preprocess: reig(bimap(s_i, Wp_i)) + cached log
  k_bimap_pre<<<1024, 256>>>(s0, s1, Wp0, Wp1);
  k_eigh<<<1024, 256>>>(0, 0);
  k_recon_pre<<<1024, 256>>>();

  const int offs[3] = {0, 2, 5};
  for (int s = 0; s < 3; s++) {
    int J = 2 + s, o = offs[s], ns = 2 + s;
    int nb = J * 3 * 512;
    k_bimap_step<<<nb, 256>>>(Wop, o);
    k_eigh<<<nb, 256>>>(0, 0);
    k_recon_log<<<nb, 256>>>();
    k_mean<<<512, 256>>>(wts, o, J, ns);
    k_eigh<<<512, 256>>>(1, ns * 512);
    k_recon_exp<<<512, 256>>>(ns, out);
  }
}

// round 11
// speedup vs baseline: 1.2448x; 1.1766x over previous
#include <cuda_runtime.h>
#include <math.h>

#define EPSV 1e-4f

// scratch (device globals; allocation is banned)
__device__ __align__(16) float g_B[25165824];       // 12*512 matrices of 64x64
__device__ __align__(16) float g_Vt[25165824];      // eigenvectors (cols = eigvecs)
__device__ __align__(16) float g_w[393216];         // eigenvalues
__device__ __align__(16) float g_state[10485760];   // 5*512*4096
__device__ __align__(16) float g_Lstate[10485760];  // logm(states)

// ---------------- bimap: Y = W X W^T (64x64) --------------------------------
__device__ __forceinline__ void bimap64(const float* __restrict__ X,
                                        const float* __restrict__ W,
                                        float* __restrict__ Y,
                                        float* Ws, float* Xs) {
  const int t = threadIdx.x;
  for (int i = t; i < 4096; i += 256) {
    int r = i >> 6, c = i & 63;
    Ws[r * 65 + c] = W[i];
    Xs[r * 65 + c] = X[i];
  }
  __syncthreads();
  const int i0 = (t >> 4) * 4, j0 = (t & 15) * 4;
  float acc[4][4] = {};
  for (int k = 0; k < 64; k++) {          // T = W * X
    float a[4], b[4];
#pragma unroll
    for (int r = 0; r < 4; r++) a[r] = Ws[(i0 + r) * 65 + k];
#pragma unroll
    for (int c = 0; c < 4; c++) b[c] = Xs[k * 65 + j0 + c];
#pragma unroll
    for (int r = 0; r < 4; r++)
#pragma unroll
      for (int c = 0; c < 4; c++) acc[r][c] += a[r] * b[c];
  }
  __syncthreads();
#pragma unroll
  for (int r = 0; r < 4; r++)
#pragma unroll
    for (int c = 0; c < 4; c++) Xs[(i0 + r) * 65 + j0 + c] = acc[r][c];
  __syncthreads();
  float acc2[4][4] = {};
  for (int k = 0; k < 64; k++) {          // Y = T * W^T
    float a[4], b[4];
#pragma unroll
    for (int r = 0; r < 4; r++) a[r] = Xs[(i0 + r) * 65 + k];
#pragma unroll
    for (int c = 0; c < 4; c++) b[c] = Ws[(j0 + c) * 65 + k];
#pragma unroll
    for (int r = 0; r < 4; r++)
#pragma unroll
      for (int c = 0; c < 4; c++) acc2[r][c] += a[r] * b[c];
  }
#pragma unroll
  for (int r = 0; r < 4; r++)
#pragma unroll
    for (int c = 0; c < 4; c++) Y[(i0 + r) * 64 + j0 + c] = acc2[r][c];
}

__global__ void k_bimap_pre(const float* __restrict__ s0, const float* __restrict__ s1,
                            const float* __restrict__ Wp0, const float* __restrict__ Wp1) {
  __shared__ float Ws[4160], Xs[4160];
  int m = blockIdx.x, slot = m >> 9, bc = m & 511;
  const float* X = (slot ? s1 : s0) + (size_t)bc * 4096;
  const float* W = slot ? Wp1 : Wp0;
  bimap64(X, W, g_B + (size_t)m * 4096, Ws, Xs);
}

__global__ void k_bimap_step(const float* __restrict__ Wop, int o) {
  __shared__ float Ws[4160], Xs[4160];
  int m = blockIdx.x;
  int j = m / 1536, rem = m % 1536, r = rem / 512, k = r + 1, bc = rem % 512;
  const float* X = g_state + (size_t)(j * 512 + bc) * 4096;
  const float* W = Wop + (size_t)((o + j) * 4 + k) * 4096;
  bimap64(X, W, g_B + (size_t)m * 4096, Ws, Xs);
}

// ---------------- batched Jacobi eigh: fused 2x2 rounds ----------------------
__global__ void __launch_bounds__(256, 4) k_eigh(int useL, int off) {
  __shared__ float As[4160], Vs[4160];
  __shared__ float red[8];
  __shared__ float snrm2;
  __shared__ int sdone;
  const int t = threadIdx.x;
  const int lane = t & 31, wid = t >> 5;
  const int m = blockIdx.x;
  const float* src = (useL ? g_Lstate : g_B) + (size_t)(off + m) * 4096;

  float loc = 0.f;
  for (int i = t; i < 4096; i += 256) {
    int r = i >> 6, c = i & 63;
    float v = 0.5f * (src[i] + src[c * 64 + r]);
    As[r * 65 + c] = v;
    Vs[r * 65 + c] = (r == c) ? 1.f : 0.f;
    loc += v * v;
  }
#pragma unroll
  for (int o2 = 16; o2; o2 >>= 1) loc += __shfl_xor_sync(~0u, loc, o2);
  if (lane == 0) red[wid] = loc;
  __syncthreads();
  if (t == 0) {
    float s = 0.f;
    for (int i = 0; i < 8; i++) s += red[i];
    snrm2 = s;
  }
  __syncthreads();

  for (int sweep = 0; sweep < 18; sweep++) {
    // convergence check: off-diagonal Frobenius^2
    float l2 = 0.f;
    for (int i = t; i < 4096; i += 256) {
      int r = i >> 6, c = i & 63;
      float v = As[r * 65 + c];
      l2 += (r != c) ? v * v : 0.f;
    }
#pragma unroll
    for (int o2 = 16; o2; o2 >>= 1) l2 += __shfl_xor_sync(~0u, l2, o2);
    if (lane == 0) red[wid] = l2;
    __syncthreads();
    if (t == 0) {
      float s = 0.f;
      for (int i = 0; i < 8; i++) s += red[i];
      sdone = (s <= 1e-11f * snrm2) ? 1 : 0;
    }
    __syncthreads();
    if (sdone) break;

    for (int mr = 1; mr < 64; mr++) {
      const int h = 31 - __clz(mr);
      const int msk = (1 << h) - 1;
      // phase a: every warp computes all 32 rotations (lane = pair index)
      const int pi = ((lane >> h) << (h + 1)) | (lane & msk);
      const int qi = pi ^ mr;
      float app = As[pi * 65 + pi];
      float aqq = As[qi * 65 + qi];
      float apq = As[pi * 65 + qi];
      float cc = 1.f, ss = 0.f;
      if (fabsf(apq) > 1e-37f) {
        float tau = (aqq - app) / (2.f * apq);
        float tt = copysignf(1.f, tau) / (fabsf(tau) + sqrtf(1.f + tau * tau));
        cc = rsqrtf(1.f + tt * tt);
        ss = tt * cc;
      }
      __syncthreads();  // rotation reads done before block writes

      // phase b: fused two-sided update. Thread (wid,lane) owns A blocks
      // (i=lane, j=wid+8k) and V col-pairs j at rows lane, lane+32.
#pragma unroll
      for (int k = 0; k < 4; k++) {
        const int j = wid + 8 * k;
        const float cj = __shfl_sync(~0u, cc, j);
        const float sj = __shfl_sync(~0u, ss, j);
        const int pj = ((j >> h) << (h + 1)) | (j & msk);
        const int qj = pj ^ mr;

        float b00 = As[pi * 65 + pj], b01 = As[pi * 65 + qj];
        float b10 = As[qi * 65 + pj], b11 = As[qi * 65 + qj];
        float t00 = cc * b00 - ss * b10, t01 = cc * b01 - ss * b11;
        float t10 = ss * b00 + cc * b10, t11 = ss * b01 + cc * b11;
        As[pi * 65 + pj] = t00 * cj - t01 * sj;
        As[pi * 65 + qj] = t00 * sj + t01 * cj;
        As[qi * 65 + pj] = t10 * cj - t11 * sj;
        As[qi * 65 + qj] = t10 * sj + t11 * cj;

        float vp0 = Vs[lane * 65 + pj], vq0 = Vs[lane * 65 + qj];
        Vs[lane * 65 + pj] = cj * vp0 - sj * vq0;
        Vs[lane * 65 + qj] = sj * vp0 + cj * vq0;
        float vp1 = Vs[(lane + 32) * 65 + pj], vq1 = Vs[(lane + 32) * 65 + qj];
        Vs[(lane + 32) * 65 + pj] = cj * vp1 - sj * vq1;
        Vs[(lane + 32) * 65 + qj] = sj * vp1 + cj * vq1;
      }
      __syncthreads();
    }
  }
  if (t < 64) g_w[(size_t)m * 64 + t] = As[t * 65 + t];
  for (int i = t; i < 4096; i += 256)
    g_Vt[(size_t)m * 4096 + i] = Vs[(i >> 6) * 65 + (i & 63)];
}

// ---------------- reconstructions V f(w) V^T --------------------------------
__global__ void k_recon_pre() {  // state = V clip(w) V^T ; Lstate = V log(clip(w)) V^T
  __shared__ float Vs[4160], fc[64], fl[64];
  const int m = blockIdx.x, t = threadIdx.x;
  const int slot = m >> 9, bc = m & 511;
  const float* V = g_Vt + (size_t)m * 4096;
  for (int i = t; i < 4096; i += 256) Vs[(i >> 6) * 65 + (i & 63)] = V[i];
  if (t < 64) {
    float cw = fmaxf(g_w[(size_t)m * 64 + t], EPSV);
    fc[t] = cw; fl[t] = logf(cw);
  }
  __syncthreads();
  const int i0 = (t >> 4) * 4, j0 = (t & 15) * 4;
  float a[4][4] = {}, b[4][4] = {};
  for (int k = 0; k < 64; k++) {
    float u[4], v[4];
#pragma unroll
    for (int r = 0; r < 4; r++) u[r] = Vs[(i0 + r) * 65 + k];
#pragma unroll
    for (int c = 0; c < 4; c++) v[c] = Vs[(j0 + c) * 65 + k];
    float fck = fc[k], flk = fl[k];
#pragma unroll
    for (int r = 0; r < 4; r++)
#pragma unroll
      for (int c = 0; c < 4; c++) {
        float p = u[r] * v[c];
        a[r][c] += p * fck;
        b[r][c] += p * flk;
      }
  }
  float* st = g_state + (size_t)(slot * 512 + bc) * 4096;
  float* ls = g_Lstate + (size_t)(slot * 512 + bc) * 4096;
#pragma unroll
  for (int r = 0; r < 4; r++)
#pragma unroll
    for (int c = 0; c < 4; c++) {
      st[(i0 + r) * 64 + j0 + c] = a[r][c];
      ls[(i0 + r) * 64 + j0 + c] = b[r][c];
    }
}

__global__ void k_recon_log() {  // g_B[m] = V log(clip(w)) V^T
  __shared__ float Vs[4160], fl[64];
  const int m = blockIdx.x, t = threadIdx.x;
  const float* V = g_Vt + (size_t)m * 4096;
  for (int i = t; i < 4096; i += 256) Vs[(i >> 6) * 65 + (i & 63)] = V[i];
  if (t < 64) fl[t] = logf(fmaxf(g_w[(size_t)m * 64 + t], EPSV));
  __syncthreads();
  const int i0 = (t >> 4) * 4, j0 = (t & 15) * 4;
  float a[4][4] = {};
  for (int k = 0; k < 64; k++) {
    float u[4], v[4];
#pragma unroll
    for (int r = 0; r < 4; r++) u[r] = Vs[(i0 + r) * 65 + k];
#pragma unroll
    for (int c = 0; c < 4; c++) v[c] = Vs[(j0 + c) * 65 + k] * fl[k];
#pragma unroll
    for (int r = 0; r < 4; r++)
#pragma unroll
      for (int c = 0; c < 4; c++) a[r][c] += u[r] * v[c];
  }
  float* dst = g_B + (size_t)m * 4096;
#pragma unroll
  for (int r = 0; r < 4; r++)
#pragma unroll
    for (int c = 0; c < 4; c++) dst[(i0 + r) * 64 + j0 + c] = a[r][c];
}

__global__ void k_recon_exp(int ns, float* __restrict__ out) {  // state = V exp(w) V^T
  __shared__ float Vs[4160], fe[64];
  const int m = blockIdx.x, t = threadIdx.x;
  const float* V = g_Vt + (size_t)m * 4096;
  for (int i = t; i < 4096; i += 256) Vs[(i >> 6) * 65 + (i & 63)] = V[i];
  if (t < 64) fe[t] = expf(g_w[(size_t)m * 64 + t]);
  __syncthreads();
  const int i0 = (t >> 4) * 4, j0 = (t & 15) * 4;
  float a[4][4] = {};
  for (int k = 0; k < 64; k++) {
    float u[4], v[4];
#pragma unroll
    for (int r = 0; r < 4; r++) u[r] = Vs[(i0 + r) * 65 + k];
#pragma unroll
    for (int c = 0; c < 4; c++) v[c] = Vs[(j0 + c) * 65 + k] * fe[k];
#pragma unroll
    for (int r = 0; r < 4; r++)
#pragma unroll
      for (int c = 0; c < 4; c++) a[r][c] += u[r] * v[c];
  }
  float* st = g_state + (size_t)(ns * 512 + m) * 4096;
  int b = m >> 4, c0 = m & 15;
  float* od = out + (size_t)((b * 48 + (ns - 2) * 16 + c0)) * 4096;
#pragma unroll
  for (int r = 0; r < 4; r++)
#pragma unroll
    for (int c = 0; c < 4; c++) {
      float v = a[r][c];
      st[(i0 + r) * 64 + j0 + c] = v;
      od[(i0 + r) * 64 + j0 + c] = v;
    }
}

// ---------------- mean of weighted logs --------------------------------------
__global__ void k_mean(const float* __restrict__ wts, int o, int J, int ns) {
  const int bc = blockIdx.x, t = threadIdx.x;
  float wl[4][4];
  for (int j = 0; j < J; j++)
    for (int k = 0; k < 4; k++) wl[j][k] = wts[(o + j) * 4 + k];
  const float inv = 1.f / (float)J;
  float* dst = g_Lstate + (size_t)(ns * 512 + bc) * 4096;
  for (int e = t; e < 4096; e += 256) {
    float acc = 0.f;
    for (int j = 0; j < J; j++) {
      acc += wl[j][0] * g_Lstate[(size_t)(j * 512 + bc) * 4096 + e];
      for (int r = 0; r < 3; r++)
        acc += wl[j][r + 1] * g_B[(size_t)((j * 3 + r) * 512 + bc) * 4096 + e];
    }
    dst[e] = acc * inv;
  }
}

// ---------------- host ---------------------------------------------------------
extern "C" void kernel_launch(void* const* d_in, const int* in_sizes, int n_in,
                              void* d_out, int out_size) {
  const float* s0  = (const float*)d_in[0];
  const float* s1  = (const float*)d_in[1];
  const float* wts = (const float*)d_in[2];
  const float* Wp0 = (const float*)d_in[3];
  const float* Wp1 = (const float*)d_in[4];
  const float* Wop = (const float*)d_in[5];
  float* out = (float*)d_out;
  (void)in_sizes; (void)n_in; (void)out_size;

  // preprocess: reig(bimap(s_i, Wp_i)) + cached log
  k_bimap_pre<<<1024, 256>>>(s0, s1, Wp0, Wp1);
  k_eigh<<<1024, 256>>>(0, 0);
  k_recon_pre<<<1024, 256>>>();

  const int offs[3] = {0, 2, 5};
  for (int s = 0; s < 3; s++) {
    int J = 2 + s, o = offs[s], ns = 2 + s;
    int nb = J * 3 * 512;
    k_bimap_step<<<nb, 256>>>(Wop, o);
    k_eigh<<<nb, 256>>>(0, 0);
    k_recon_log<<<nb, 256>>>();
    k_mean<<<512, 256>>>(wts, o, J, ns);
    k_eigh<<<512, 256>>>(1, ns * 512);
    k_recon_exp<<<512, 256>>>(ns, out);
  }
}

// round 12
// speedup vs baseline: 1.3386x; 1.0753x over previous
#include <cuda_runtime.h>
#include <math.h>

#define EPSV 1e-4f

// scratch (device globals; allocation is banned)
__device__ __align__(16) float g_B[25165824];       // 12*512 matrices of 64x64
__device__ __align__(16) float g_Vt[25165824];      // eigenvectors (cols = eigvecs)
__device__ __align__(16) float g_w[393216];         // eigenvalues
__device__ __align__(16) float g_state[10485760];   // 5*512*4096
__device__ __align__(16) float g_Lstate[10485760];  // logm(states)

// ---------------- bimap: Y = W X W^T (64x64) --------------------------------
__device__ __forceinline__ void bimap64(const float* __restrict__ X,
                                        const float* __restrict__ W,
                                        float* __restrict__ Y,
                                        float* Ws, float* Xs) {
  const int t = threadIdx.x;
  for (int i = t; i < 4096; i += 256) {
    int r = i >> 6, c = i & 63;
    Ws[r * 65 + c] = W[i];
    Xs[r * 65 + c] = X[i];
  }
  __syncthreads();
  const int i0 = (t >> 4) * 4, j0 = (t & 15) * 4;
  float acc[4][4] = {};
  for (int k = 0; k < 64; k++) {          // T = W * X
    float a[4], b[4];
#pragma unroll
    for (int r = 0; r < 4; r++) a[r] = Ws[(i0 + r) * 65 + k];
#pragma unroll
    for (int c = 0; c < 4; c++) b[c] = Xs[k * 65 + j0 + c];
#pragma unroll
    for (int r = 0; r < 4; r++)
#pragma unroll
      for (int c = 0; c < 4; c++) acc[r][c] += a[r] * b[c];
  }
  __syncthreads();
#pragma unroll
  for (int r = 0; r < 4; r++)
#pragma unroll
    for (int c = 0; c < 4; c++) Xs[(i0 + r) * 65 + j0 + c] = acc[r][c];
  __syncthreads();
  float acc2[4][4] = {};
  for (int k = 0; k < 64; k++) {          // Y = T * W^T
    float a[4], b[4];
#pragma unroll
    for (int r = 0; r < 4; r++) a[r] = Xs[(i0 + r) * 65 + k];
#pragma unroll
    for (int c = 0; c < 4; c++) b[c] = Ws[(j0 + c) * 65 + k];
#pragma unroll
    for (int r = 0; r < 4; r++)
#pragma unroll
      for (int c = 0; c < 4; c++) acc2[r][c] += a[r] * b[c];
  }
#pragma unroll
  for (int r = 0; r < 4; r++)
#pragma unroll
    for (int c = 0; c < 4; c++) Y[(i0 + r) * 64 + j0 + c] = acc2[r][c];
}

__global__ void k_bimap_pre(const float* __restrict__ s0, const float* __restrict__ s1,
                            const float* __restrict__ Wp0, const float* __restrict__ Wp1) {
  __shared__ float Ws[4160], Xs[4160];
  int m = blockIdx.x, slot = m >> 9, bc = m & 511;
  const float* X = (slot ? s1 : s0) + (size_t)bc * 4096;
  const float* W = slot ? Wp1 : Wp0;
  bimap64(X, W, g_B + (size_t)m * 4096, Ws, Xs);
}

__global__ void k_bimap_step(const float* __restrict__ Wop, int o) {
  __shared__ float Ws[4160], Xs[4160];
  int m = blockIdx.x;
  int j = m / 1536, rem = m % 1536, r = rem / 512, k = r + 1, bc = rem % 512;
  const float* X = g_state + (size_t)(j * 512 + bc) * 4096;
  const float* W = Wop + (size_t)((o + j) * 4 + k) * 4096;
  bimap64(X, W, g_B + (size_t)m * 4096, Ws, Xs);
}

// ---------------- batched Jacobi eigh: 128 threads, 4-warp barriers ----------
__global__ void __launch_bounds__(128, 8) k_eigh(int useL, int off) {
  __shared__ float As[4160], Vs[4160];
  __shared__ float red[4];
  const int t = threadIdx.x;
  const int lane = t & 31, wid = t >> 5;   // wid 0..3
  const int m = blockIdx.x;
  const float* src = (useL ? g_Lstate : g_B) + (size_t)(off + m) * 4096;

  float loc = 0.f;
  for (int i = t; i < 4096; i += 128) {
    int r = i >> 6, c = i & 63;
    float v = 0.5f * (src[i] + src[c * 64 + r]);
    As[r * 65 + c] = v;
    Vs[r * 65 + c] = (r == c) ? 1.f : 0.f;
    loc += v * v;
  }
#pragma unroll
  for (int o2 = 16; o2; o2 >>= 1) loc += __shfl_xor_sync(~0u, loc, o2);
  if (lane == 0) red[wid] = loc;
  __syncthreads();
  const float thr = (red[0] + red[1] + red[2] + red[3]) * 1e-11f;
  __syncthreads();   // everyone read red before the first check overwrites it

  for (int sweep = 0; sweep < 18; sweep++) {
    // convergence check: off-diagonal Frobenius^2 (all threads same decision)
    float l2 = 0.f;
    for (int i = t; i < 4096; i += 128) {
      int r = i >> 6, c = i & 63;
      float v = As[r * 65 + c];
      l2 += (r != c) ? v * v : 0.f;
    }
#pragma unroll
    for (int o2 = 16; o2; o2 >>= 1) l2 += __shfl_xor_sync(~0u, l2, o2);
    if (lane == 0) red[wid] = l2;
    __syncthreads();
    if (red[0] + red[1] + red[2] + red[3] <= thr) break;

    for (int mr = 1; mr < 64; mr++) {
      const int h = 31 - __clz(mr);
      const int msk = (1 << h) - 1;
      // phase a: every warp computes all 32 rotations (lane = pair index)
      const int pi = ((lane >> h) << (h + 1)) | (lane & msk);
      const int qi = pi ^ mr;
      float app = As[pi * 65 + pi];
      float aqq = As[qi * 65 + qi];
      float apq = As[pi * 65 + qi];
      float cc = 1.f, ss = 0.f;
      if (fabsf(apq) > 1e-37f) {
        float tau = (aqq - app) / (2.f * apq);
        float tt = copysignf(1.f, tau) / (fabsf(tau) + sqrtf(1.f + tau * tau));
        cc = rsqrtf(1.f + tt * tt);
        ss = tt * cc;
      }
      __syncthreads();  // rotation reads done before block writes

      // phase b: fused two-sided update. Thread (wid,lane) owns A blocks
      // (i=lane, j=wid+4k, k<8) and V col-pairs j at rows lane, lane+32.
#pragma unroll
      for (int k = 0; k < 8; k++) {
        const int j = wid + 4 * k;
        const float cj = __shfl_sync(~0u, cc, j);
        const float sj = __shfl_sync(~0u, ss, j);
        const int pj = ((j >> h) << (h + 1)) | (j & msk);
        const int qj = pj ^ mr;

        float b00 = As[pi * 65 + pj], b01 = As[pi * 65 + qj];
        float b10 = As[qi * 65 + pj], b11 = As[qi * 65 + qj];
        float t00 = cc * b00 - ss * b10, t01 = cc * b01 - ss * b11;
        float t10 = ss * b00 + cc * b10, t11 = ss * b01 + cc * b11;
        As[pi * 65 + pj] = t00 * cj - t01 * sj;
        As[pi * 65 + qj] = t00 * sj + t01 * cj;
        As[qi * 65 + pj] = t10 * cj - t11 * sj;
        As[qi * 65 + qj] = t10 * sj + t11 * cj;

        float vp0 = Vs[lane * 65 + pj], vq0 = Vs[lane * 65 + qj];
        Vs[lane * 65 + pj] = cj * vp0 - sj * vq0;
        Vs[lane * 65 + qj] = sj * vp0 + cj * vq0;
        float vp1 = Vs[(lane + 32) * 65 + pj], vq1 = Vs[(lane + 32) * 65 + qj];
        Vs[(lane + 32) * 65 + pj] = cj * vp1 - sj * vq1;
        Vs[(lane + 32) * 65 + qj] = sj * vp1 + cj * vq1;
      }
      __syncthreads();
    }
  }
  if (t < 64) g_w[(size_t)m * 64 + t] = As[t * 65 + t];
  for (int i = t; i < 4096; i += 128)
    g_Vt[(size_t)m * 4096 + i] = Vs[(i >> 6) * 65 + (i & 63)];
}

// ---------------- reconstructions V f(w) V^T --------------------------------
__global__ void k_recon_pre() {  // state = V clip(w) V^T ; Lstate = V log(clip(w)) V^T
  __shared__ float Vs[4160], fc[64], fl[64];
  const int m = blockIdx.x, t = threadIdx.x;
  const int slot = m >> 9, bc = m & 511;
  const float* V = g_Vt + (size_t)m * 4096;
  for (int i = t; i < 4096; i += 256) Vs[(i >> 6) * 65 + (i & 63)] = V[i];
  if (t < 64) {
    float cw = fmaxf(g_w[(size_t)m * 64 + t], EPSV);
    fc[t] = cw; fl[t] = logf(cw);
  }
  __syncthreads();
  const int i0 = (t >> 4) * 4, j0 = (t & 15) * 4;
  float a[4][4] = {}, b[4][4] = {};
  for (int k = 0; k < 64; k++) {
    float u[4], v[4];
#pragma unroll
    for (int r = 0; r < 4; r++) u[r] = Vs[(i0 + r) * 65 + k];
#pragma unroll
    for (int c = 0; c < 4; c++) v[c] = Vs[(j0 + c) * 65 + k];
    float fck = fc[k], flk = fl[k];
#pragma unroll
    for (int r = 0; r < 4; r++)
#pragma unroll
      for (int c = 0; c < 4; c++) {
        float p = u[r] * v[c];
        a[r][c] += p * fck;
        b[r][c] += p * flk;
      }
  }
  float* st = g_state + (size_t)(slot * 512 + bc) * 4096;
  float* ls = g_Lstate + (size_t)(slot * 512 + bc) * 4096;
#pragma unroll
  for (int r = 0; r < 4; r++)
#pragma unroll
    for (int c = 0; c < 4; c++) {
      st[(i0 + r) * 64 + j0 + c] = a[r][c];
      ls[(i0 + r) * 64 + j0 + c] = b[r][c];
    }
}

__global__ void k_recon_log() {  // g_B[m] = V log(clip(w)) V^T
  __shared__ float Vs[4160], fl[64];
  const int m = blockIdx.x, t = threadIdx.x;
  const float* V = g_Vt + (size_t)m * 4096;
  for (int i = t; i < 4096; i += 256) Vs[(i >> 6) * 65 + (i & 63)] = V[i];
  if (t < 64) fl[t] = logf(fmaxf(g_w[(size_t)m * 64 + t], EPSV));
  __syncthreads();
  const int i0 = (t >> 4) * 4, j0 = (t & 15) * 4;
  float a[4][4] = {};
  for (int k = 0; k < 64; k++) {
    float u[4], v[4];
#pragma unroll
    for (int r = 0; r < 4; r++) u[r] = Vs[(i0 + r) * 65 + k];
#pragma unroll
    for (int c = 0; c < 4; c++) v[c] = Vs[(j0 + c) * 65 + k] * fl[k];
#pragma unroll
    for (int r = 0; r < 4; r++)
#pragma unroll
      for (int c = 0; c < 4; c++) a[r][c] += u[r] * v[c];
  }
  float* dst = g_B + (size_t)m * 4096;
#pragma unroll
  for (int r = 0; r < 4; r++)
#pragma unroll
    for (int c = 0; c < 4; c++) dst[(i0 + r) * 64 + j0 + c] = a[r][c];
}

__global__ void k_recon_exp(int ns, float* __restrict__ out) {  // state = V exp(w) V^T
  __shared__ float Vs[4160], fe[64];
  const int m = blockIdx.x, t = threadIdx.x;
  const float* V = g_Vt + (size_t)m * 4096;
  for (int i = t; i < 4096; i += 256) Vs[(i >> 6) * 65 + (i & 63)] = V[i];
  if (t < 64) fe[t] = expf(g_w[(size_t)m * 64 + t]);
  __syncthreads();
  const int i0 = (t >> 4) * 4, j0 = (t & 15) * 4;
  float a[4][4] = {};
  for (int k = 0; k < 64; k++) {
    float u[4], v[4];
#pragma unroll
    for (int r = 0; r < 4; r++) u[r] = Vs[(i0 + r) * 65 + k];
#pragma unroll
    for (int c = 0; c < 4; c++) v[c] = Vs[(j0 + c) * 65 + k] * fe[k];
#pragma unroll
    for (int r = 0; r < 4; r++)
#pragma unroll
      for (int c = 0; c < 4; c++) a[r][c] += u[r] * v[c];
  }
  float* st = g_state + (size_t)(ns * 512 + m) * 4096;
  int b = m >> 4, c0 = m & 15;
  float* od = out + (size_t)((b * 48 + (ns - 2) * 16 + c0)) * 4096;
#pragma unroll
  for (int r = 0; r < 4; r++)
#pragma unroll
    for (int c = 0; c < 4; c++) {
      float v = a[r][c];
      st[(i0 + r) * 64 + j0 + c] = v;
      od[(i0 + r) * 64 + j0 + c] = v;
    }
}

// ---------------- mean of weighted logs --------------------------------------
__global__ void k_mean(const float* __restrict__ wts, int o, int J, int ns) {
  const int bc = blockIdx.x, t = threadIdx.x;
  float wl[4][4];
  for (int j = 0; j < J; j++)
    for (int k = 0; k < 4; k++) wl[j][k] = wts[(o + j) * 4 + k];
  const float inv = 1.f / (float)J;
  float* dst = g_Lstate + (size_t)(ns * 512 + bc) * 4096;
  for (int e = t; e < 4096; e += 256) {
    float acc = 0.f;
    for (int j = 0; j < J; j++) {
      acc += wl[j][0] * g_Lstate[(size_t)(j * 512 + bc) * 4096 + e];
      for (int r = 0; r < 3; r++)
        acc += wl[j][r + 1] * g_B[(size_t)((j * 3 + r) * 512 + bc) * 4096 + e];
    }
    dst[e] = acc * inv;
  }
}

// ---------------- host ---------------------------------------------------------
extern "C" void kernel_launch(void* const* d_in, const int* in_sizes, int n_in,
                              void* d_out, int out_size) {
  const float* s0  = (const float*)d_in[0];
  const float* s1  = (const float*)d_in[1];
  const float* wts = (const float*)d_in[2];
  const float* Wp0 = (const float*)d_in[3];
  const float* Wp1 = (const float*)d_in[4];
  const float* Wop = (const float*)d_in[5];
  float* out = (float*)d_out;
  (void)in_sizes; (void)n_in; (void)out_size;

  // preprocess: reig(bimap(s_i, Wp_i)) + cached log
  k_bimap_pre<<<1024, 256>>>(s0, s1, Wp0, Wp1);
  k_eigh<<<1024, 128>>>(0, 0);
  k_recon_pre<<<1024, 256>>>();

  const int offs[3] = {0, 2, 5};
  for (int s = 0; s < 3; s++) {
    int J = 2 + s, o = offs[s], ns = 2 + s;
    int nb = J * 3 * 512;
    k_bimap_step<<<nb, 256>>>(Wop, o);
    k_eigh<<<nb, 128>>>(0, 0);
    k_recon_log<<<nb, 256>>>();
    k_mean<<<512, 256>>>(wts, o, J, ns);
    k_eigh<<<512, 128>>>(1, ns * 512);
    k_recon_exp<<<512, 256>>>(ns, out);
  }
}

// round 13
// speedup vs baseline: 1.3789x; 1.0301x over previous
#include <cuda_runtime.h>
#include <math.h>

#define EPSV 1e-4f

// scratch (device globals; allocation is banned)
__device__ __align__(16) float g_B[25165824];       // 12*512 matrices of 64x64
__device__ __align__(16) float g_Vt[25165824];      // eigenvectors (cols = eigvecs)
__device__ __align__(16) float g_w[393216];         // eigenvalues
__device__ __align__(16) float g_state[10485760];   // 5*512*4096
__device__ __align__(16) float g_Lstate[10485760];  // logm(states)

// ---------------- bimap: Y = W X W^T (64x64) --------------------------------
__device__ __forceinline__ void bimap64(const float* __restrict__ X,
                                        const float* __restrict__ W,
                                        float* __restrict__ Y,
                                        float* Ws, float* Xs) {
  const int t = threadIdx.x;
  for (int i = t; i < 4096; i += 256) {
    int r = i >> 6, c = i & 63;
    Ws[r * 65 + c] = W[i];
    Xs[r * 65 + c] = X[i];
  }
  __syncthreads();
  const int i0 = (t >> 4) * 4, j0 = (t & 15) * 4;
  float acc[4][4] = {};
  for (int k = 0; k < 64; k++) {          // T = W * X
    float a[4], b[4];
#pragma unroll
    for (int r = 0; r < 4; r++) a[r] = Ws[(i0 + r) * 65 + k];
#pragma unroll
    for (int c = 0; c < 4; c++) b[c] = Xs[k * 65 + j0 + c];
#pragma unroll
    for (int r = 0; r < 4; r++)
#pragma unroll
      for (int c = 0; c < 4; c++) acc[r][c] += a[r] * b[c];
  }
  __syncthreads();
#pragma unroll
  for (int r = 0; r < 4; r++)
#pragma unroll
    for (int c = 0; c < 4; c++) Xs[(i0 + r) * 65 + j0 + c] = acc[r][c];
  __syncthreads();
  float acc2[4][4] = {};
  for (int k = 0; k < 64; k++) {          // Y = T * W^T
    float a[4], b[4];
#pragma unroll
    for (int r = 0; r < 4; r++) a[r] = Xs[(i0 + r) * 65 + k];
#pragma unroll
    for (int c = 0; c < 4; c++) b[c] = Ws[(j0 + c) * 65 + k];
#pragma unroll
    for (int r = 0; r < 4; r++)
#pragma unroll
      for (int c = 0; c < 4; c++) acc2[r][c] += a[r] * b[c];
  }
#pragma unroll
  for (int r = 0; r < 4; r++)
#pragma unroll
    for (int c = 0; c < 4; c++) Y[(i0 + r) * 64 + j0 + c] = acc2[r][c];
}

__global__ void k_bimap_pre(const float* __restrict__ s0, const float* __restrict__ s1,
                            const float* __restrict__ Wp0, const float* __restrict__ Wp1) {
  __shared__ float Ws[4160], Xs[4160];
  int m = blockIdx.x, slot = m >> 9, bc = m & 511;
  const float* X = (slot ? s1 : s0) + (size_t)bc * 4096;
  const float* W = slot ? Wp1 : Wp0;
  bimap64(X, W, g_B + (size_t)m * 4096, Ws, Xs);
}

__global__ void k_bimap_step(const float* __restrict__ Wop, int o) {
  __shared__ float Ws[4160], Xs[4160];
  int m = blockIdx.x;
  int j = m / 1536, rem = m % 1536, r = rem / 512, k = r + 1, bc = rem % 512;
  const float* X = g_state + (size_t)(j * 512 + bc) * 4096;
  const float* W = Wop + (size_t)((o + j) * 4 + k) * 4096;
  bimap64(X, W, g_B + (size_t)m * 4096, Ws, Xs);
}

// ---------------- batched Jacobi eigh: threshold skips, 128 threads ----------
__global__ void __launch_bounds__(128, 8) k_eigh(int useL, int off) {
  __shared__ float As[4160], Vs[4160];
  __shared__ float red[4];
  const int t = threadIdx.x;
  const int lane = t & 31, wid = t >> 5;   // wid 0..3
  const int m = blockIdx.x;
  const float* src = (useL ? g_Lstate : g_B) + (size_t)(off + m) * 4096;

  float loc = 0.f;
  for (int i = t; i < 4096; i += 128) {
    int r = i >> 6, c = i & 63;
    float v = 0.5f * (src[i] + src[c * 64 + r]);
    As[r * 65 + c] = v;
    Vs[r * 65 + c] = (r == c) ? 1.f : 0.f;
    loc += v * v;
  }
#pragma unroll
  for (int o2 = 16; o2; o2 >>= 1) loc += __shfl_xor_sync(~0u, loc, o2);
  if (lane == 0) red[wid] = loc;
  __syncthreads();
  const float thr = (red[0] + red[1] + red[2] + red[3]) * 1e-11f;
  const float skipthr = thr * (1.f / 2016.f);  // per-pair trivial threshold
  __syncthreads();   // everyone read red before the first check overwrites it

  for (int sweep = 0; sweep < 18; sweep++) {
    // convergence check: off-diagonal Frobenius^2 (all threads same decision)
    float l2 = 0.f;
    for (int i = t; i < 4096; i += 128) {
      int r = i >> 6, c = i & 63;
      float v = As[r * 65 + c];
      l2 += (r != c) ? v * v : 0.f;
    }
#pragma unroll
    for (int o2 = 16; o2; o2 >>= 1) l2 += __shfl_xor_sync(~0u, l2, o2);
    if (lane == 0) red[wid] = l2;
    __syncthreads();
    if (red[0] + red[1] + red[2] + red[3] <= thr) break;

    for (int mr = 1; mr < 64; mr++) {
      const int h = 31 - __clz(mr);
      const int msk = (1 << h) - 1;
      // phase a: every warp computes all 32 rotations (lane = pair index)
      const int pi = ((lane >> h) << (h + 1)) | (lane & msk);
      const int qi = pi ^ mr;
      float app = As[pi * 65 + pi];
      float aqq = As[qi * 65 + qi];
      float apq = As[pi * 65 + qi];
      float cc = 1.f, ss = 0.f;
      if (apq * apq > skipthr) {
        float tau = (aqq - app) / (2.f * apq);
        float tt = copysignf(1.f, tau) / (fabsf(tau) + sqrtf(1.f + tau * tau));
        cc = rsqrtf(1.f + tt * tt);
        ss = tt * cc;
      }
      const int allTi = __all_sync(~0u, ss == 0.f);  // all i-rotations trivial
      __syncthreads();  // rotation reads done before block writes

      // phase b: fused two-sided update. Thread (wid,lane) owns A blocks
      // (i=lane, j=wid+4k, k<8) and V col-pairs j at rows lane, lane+32.
#pragma unroll
      for (int k = 0; k < 8; k++) {
        const int j = wid + 4 * k;
        const float cj = __shfl_sync(~0u, cc, j);
        const float sj = __shfl_sync(~0u, ss, j);
        const int tj = (sj == 0.f);                  // warp-uniform
        const int pj = ((j >> h) << (h + 1)) | (j & msk);
        const int qj = pj ^ mr;

        if (!(tj & allTi)) {
          float b00 = As[pi * 65 + pj], b01 = As[pi * 65 + qj];
          float b10 = As[qi * 65 + pj], b11 = As[qi * 65 + qj];
          float t00 = cc * b00 - ss * b10, t01 = cc * b01 - ss * b11;
          float t10 = ss * b00 + cc * b10, t11 = ss * b01 + cc * b11;
          As[pi * 65 + pj] = t00 * cj - t01 * sj;
          As[pi * 65 + qj] = t00 * sj + t01 * cj;
          As[qi * 65 + pj] = t10 * cj - t11 * sj;
          As[qi * 65 + qj] = t10 * sj + t11 * cj;
        }
        if (!tj) {
          float vp0 = Vs[lane * 65 + pj], vq0 = Vs[lane * 65 + qj];
          Vs[lane * 65 + pj] = cj * vp0 - sj * vq0;
          Vs[lane * 65 + qj] = sj * vp0 + cj * vq0;
          float vp1 = Vs[(lane + 32) * 65 + pj], vq1 = Vs[(lane + 32) * 65 + qj];
          Vs[(lane + 32) * 65 + pj] = cj * vp1 - sj * vq1;
          Vs[(lane + 32) * 65 + qj] = sj * vp1 + cj * vq1;
        }
      }
      __syncthreads();
    }
  }
  if (t < 64) g_w[(size_t)m * 64 + t] = As[t * 65 + t];
  for (int i = t; i < 4096; i += 128)
    g_Vt[(size_t)m * 4096 + i] = Vs[(i >> 6) * 65 + (i & 63)];
}

// ---------------- reconstructions V f(w) V^T --------------------------------
__global__ void k_recon_pre() {  // state = V clip(w) V^T ; Lstate = V log(clip(w)) V^T
  __shared__ float Vs[4160], fc[64], fl[64];
  const int m = blockIdx.x, t = threadIdx.x;
  const int slot = m >> 9, bc = m & 511;
  const float* V = g_Vt + (size_t)m * 4096;
  for (int i = t; i < 4096; i += 256) Vs[(i >> 6) * 65 + (i & 63)] = V[i];
  if (t < 64) {
    float cw = fmaxf(g_w[(size_t)m * 64 + t], EPSV);
    fc[t] = cw; fl[t] = logf(cw);
  }
  __syncthreads();
  const int i0 = (t >> 4) * 4, j0 = (t & 15) * 4;
  float a[4][4] = {}, b[4][4] = {};
  for (int k = 0; k < 64; k++) {
    float u[4], v[4];
#pragma unroll
    for (int r = 0; r < 4; r++) u[r] = Vs[(i0 + r) * 65 + k];
#pragma unroll
    for (int c = 0; c < 4; c++) v[c] = Vs[(j0 + c) * 65 + k];
    float fck = fc[k], flk = fl[k];
#pragma unroll
    for (int r = 0; r < 4; r++)
#pragma unroll
      for (int c = 0; c < 4; c++) {
        float p = u[r] * v[c];
        a[r][c] += p * fck;
        b[r][c] += p * flk;
      }
  }
  float* st = g_state + (size_t)(slot * 512 + bc) * 4096;
  float* ls = g_Lstate + (size_t)(slot * 512 + bc) * 4096;
#pragma unroll
  for (int r = 0; r < 4; r++)
#pragma unroll
    for (int c = 0; c < 4; c++) {
      st[(i0 + r) * 64 + j0 + c] = a[r][c];
      ls[(i0 + r) * 64 + j0 + c] = b[r][c];
    }
}

__global__ void k_recon_log() {  // g_B[m] = V log(clip(w)) V^T
  __shared__ float Vs[4160], fl[64];
  const int m = blockIdx.x, t = threadIdx.x;
  const float* V = g_Vt + (size_t)m * 4096;
  for (int i = t; i < 4096; i += 256) Vs[(i >> 6) * 65 + (i & 63)] = V[i];
  if (t < 64) fl[t] = logf(fmaxf(g_w[(size_t)m * 64 + t], EPSV));
  __syncthreads();
  const int i0 = (t >> 4) * 4, j0 = (t & 15) * 4;
  float a[4][4] = {};
  for (int k = 0; k < 64; k++) {
    float u[4], v[4];
#pragma unroll
    for (int r = 0; r < 4; r++) u[r] = Vs[(i0 + r) * 65 + k];
#pragma unroll
    for (int c = 0; c < 4; c++) v[c] = Vs[(j0 + c) * 65 + k] * fl[k];
#pragma unroll
    for (int r = 0; r < 4; r++)
#pragma unroll
      for (int c = 0; c < 4; c++) a[r][c] += u[r] * v[c];
  }
  float* dst = g_B + (size_t)m * 4096;
#pragma unroll
  for (int r = 0; r < 4; r++)
#pragma unroll
    for (int c = 0; c < 4; c++) dst[(i0 + r) * 64 + j0 + c] = a[r][c];
}

__global__ void k_recon_exp(int ns, float* __restrict__ out) {  // state = V exp(w) V^T
  __shared__ float Vs[4160], fe[64];
  const int m = blockIdx.x, t = threadIdx.x;
  const float* V = g_Vt + (size_t)m * 4096;
  for (int i = t; i < 4096; i += 256) Vs[(i >> 6) * 65 + (i & 63)] = V[i];
  if (t < 64) fe[t] = expf(g_w[(size_t)m * 64 + t]);
  __syncthreads();
  const int i0 = (t >> 4) * 4, j0 = (t & 15) * 4;
  float a[4][4] = {};
  for (int k = 0; k < 64; k++) {
    float u[4], v[4];
#pragma unroll
    for (int r = 0; r < 4; r++) u[r] = Vs[(i0 + r) * 65 + k];
#pragma unroll
    for (int c = 0; c < 4; c++) v[c] = Vs[(j0 + c) * 65 + k] * fe[k];
#pragma unroll
    for (int r = 0; r < 4; r++)
#pragma unroll
      for (int c = 0; c < 4; c++) a[r][c] += u[r] * v[c];
  }
  float* st = g_state + (size_t)(ns * 512 + m) * 4096;
  int b = m >> 4, c0 = m & 15;
  float* od = out + (size_t)((b * 48 + (ns - 2) * 16 + c0)) * 4096;
#pragma unroll
  for (int r = 0; r < 4; r++)
#pragma unroll
    for (int c = 0; c < 4; c++) {
      float v = a[r][c];
      st[(i0 + r) * 64 + j0 + c] = v;
      od[(i0 + r) * 64 + j0 + c] = v;
    }
}

// ---------------- mean of weighted logs --------------------------------------
__global__ void k_mean(const float* __restrict__ wts, int o, int J, int ns) {
  const int bc = blockIdx.x, t = threadIdx.x;
  float wl[4][4];
  for (int j = 0; j < J; j++)
    for (int k = 0; k < 4; k++) wl[j][k] = wts[(o + j) * 4 + k];
  const float inv = 1.f / (float)J;
  float* dst = g_Lstate + (size_t)(ns * 512 + bc) * 4096;
  for (int e = t; e < 4096; e += 256) {
    float acc = 0.f;
    for (int j = 0; j < J; j++) {
      acc += wl[j][0] * g_Lstate[(size_t)(j * 512 + bc) * 4096 + e];
      for (int r = 0; r < 3; r++)
        acc += wl[j][r + 1] * g_B[(size_t)((j * 3 + r) * 512 + bc) * 4096 + e];
    }
    dst[e] = acc * inv;
  }
}

// ---------------- host ---------------------------------------------------------
extern "C" void kernel_launch(void* const* d_in, const int* in_sizes, int n_in,
                              void* d_out, int out_size) {
  const float* s0  = (const float*)d_in[0];
  const float* s1  = (const float*)d_in[1];
  const float* wts = (const float*)d_in[2];
  const float* Wp0 = (const float*)d_in[3];
  const float* Wp1 = (const float*)d_in[4];
  const float* Wop = (const float*)d_in[5];
  float* out = (float*)d_out;
  (void)in_sizes; (void)n_in; (void)out_size;

  // preprocess: reig(bimap(s_i, Wp_i)) + cached log
  k_bimap_pre<<<1024, 256>>>(s0, s1, Wp0, Wp1);
  k_eigh<<<1024, 128>>>(0, 0);
  k_recon_pre<<<1024, 256>>>();

  const int offs[3] = {0, 2, 5};
  for (int s = 0; s < 3; s++) {
    int J = 2 + s, o = offs[s], ns = 2 + s;
    int nb = J * 3 * 512;
    k_bimap_step<<<nb, 256>>>(Wop, o);
    k_eigh<<<nb, 128>>>(0, 0);
    k_recon_log<<<nb, 256>>>();
    k_mean<<<512, 256>>>(wts, o, J, ns);
    k_eigh<<<512, 128>>>(1, ns * 512);
    k_recon_exp<<<512, 256>>>(ns, out);
  }
}

// round 14
// speedup vs baseline: 1.4538x; 1.0544x over previous
#include <cuda_runtime.h>
#include <math.h>

#define EPSV 1e-4f

// scratch (device globals; allocation is banned)
__device__ __align__(16) float g_B[25165824];       // 12*512 matrices of 64x64
__device__ __align__(16) float g_Vt[25165824];      // eigenvectors (cols = eigvecs)
__device__ __align__(16) float g_w[393216];         // eigenvalues
__device__ __align__(16) float g_state[10485760];   // 5*512*4096
__device__ __align__(16) float g_Lstate[10485760];  // logm(states)

// ---------------- bimap: Y = W X W^T (64x64) --------------------------------
__device__ __forceinline__ void bimap64(const float* __restrict__ X,
                                        const float* __restrict__ W,
                                        float* __restrict__ Y,
                                        float* Ws, float* Xs) {
  const int t = threadIdx.x;
  for (int i = t; i < 4096; i += 256) {
    int r = i >> 6, c = i & 63;
    Ws[r * 65 + c] = W[i];
    Xs[r * 65 + c] = X[i];
  }
  __syncthreads();
  const int i0 = (t >> 4) * 4, j0 = (t & 15) * 4;
  float acc[4][4] = {};
  for (int k = 0; k < 64; k++) {          // T = W * X
    float a[4], b[4];
#pragma unroll
    for (int r = 0; r < 4; r++) a[r] = Ws[(i0 + r) * 65 + k];
#pragma unroll
    for (int c = 0; c < 4; c++) b[c] = Xs[k * 65 + j0 + c];
#pragma unroll
    for (int r = 0; r < 4; r++)
#pragma unroll
      for (int c = 0; c < 4; c++) acc[r][c] += a[r] * b[c];
  }
  __syncthreads();
#pragma unroll
  for (int r = 0; r < 4; r++)
#pragma unroll
    for (int c = 0; c < 4; c++) Xs[(i0 + r) * 65 + j0 + c] = acc[r][c];
  __syncthreads();
  float acc2[4][4] = {};
  for (int k = 0; k < 64; k++) {          // Y = T * W^T
    float a[4], b[4];
#pragma unroll
    for (int r = 0; r < 4; r++) a[r] = Xs[(i0 + r) * 65 + k];
#pragma unroll
    for (int c = 0; c < 4; c++) b[c] = Ws[(j0 + c) * 65 + k];
#pragma unroll
    for (int r = 0; r < 4; r++)
#pragma unroll
      for (int c = 0; c < 4; c++) acc2[r][c] += a[r] * b[c];
  }
#pragma unroll
  for (int r = 0; r < 4; r++)
#pragma unroll
    for (int c = 0; c < 4; c++) Y[(i0 + r) * 64 + j0 + c] = acc2[r][c];
}

__global__ void k_bimap_pre(const float* __restrict__ s0, const float* __restrict__ s1,
                            const float* __restrict__ Wp0, const float* __restrict__ Wp1) {
  __shared__ float Ws[4160], Xs[4160];
  int m = blockIdx.x, slot = m >> 9, bc = m & 511;
  const float* X = (slot ? s1 : s0) + (size_t)bc * 4096;
  const float* W = slot ? Wp1 : Wp0;
  bimap64(X, W, g_B + (size_t)m * 4096, Ws, Xs);
}

__global__ void k_bimap_step(const float* __restrict__ Wop, int o) {
  __shared__ float Ws[4160], Xs[4160];
  int m = blockIdx.x;
  int j = m / 1536, rem = m % 1536, r = rem / 512, k = r + 1, bc = rem % 512;
  const float* X = g_state + (size_t)(j * 512 + bc) * 4096;
  const float* W = Wop + (size_t)((o + j) * 4 + k) * 4096;
  bimap64(X, W, g_B + (size_t)m * 4096, Ws, Xs);
}

// ---------------- batched Jacobi eigh: adaptive threshold skips --------------
__global__ void __launch_bounds__(128, 8) k_eigh(int useL, int off) {
  __shared__ float As[4160], Vs[4160];
  __shared__ float red[4];
  const int t = threadIdx.x;
  const int lane = t & 31, wid = t >> 5;   // wid 0..3
  const int m = blockIdx.x;
  const float* src = (useL ? g_Lstate : g_B) + (size_t)(off + m) * 4096;

  float loc = 0.f;
  for (int i = t; i < 4096; i += 128) {
    int r = i >> 6, c = i & 63;
    float v = 0.5f * (src[i] + src[c * 64 + r]);
    As[r * 65 + c] = v;
    Vs[r * 65 + c] = (r == c) ? 1.f : 0.f;
    loc += v * v;
  }
#pragma unroll
  for (int o2 = 16; o2; o2 >>= 1) loc += __shfl_xor_sync(~0u, loc, o2);
  if (lane == 0) red[wid] = loc;
  __syncthreads();
  const float thr = (red[0] + red[1] + red[2] + red[3]) * 1e-10f;

  for (int sweep = 0; sweep < 18; sweep++) {
    // convergence check: off-diagonal Frobenius^2 (all threads same decision)
    float l2 = 0.f;
    for (int i = t; i < 4096; i += 128) {
      int r = i >> 6, c = i & 63;
      float v = As[r * 65 + c];
      l2 += (r != c) ? v * v : 0.f;
    }
#pragma unroll
    for (int o2 = 16; o2; o2 >>= 1) l2 += __shfl_xor_sync(~0u, l2, o2);
    __syncthreads();                 // WAR guard (warps may drift in trivial rounds)
    if (lane == 0) red[wid] = l2;
    __syncthreads();
    const float sumoff = red[0] + red[1] + red[2] + red[3];
    if (sumoff <= thr) break;
    // adaptive per-pair trivial threshold: skipped mass <= 1% of current off^2
    const float skipthr = fmaxf(thr, sumoff * 0.01f) * (1.f / 2016.f);

    for (int mr = 1; mr < 64; mr++) {
      const int h = 31 - __clz(mr);
      const int msk = (1 << h) - 1;
      // phase a: every warp computes all 32 rotations (lane = pair index)
      const int pi = ((lane >> h) << (h + 1)) | (lane & msk);
      const int qi = pi ^ mr;
      float app = As[pi * 65 + pi];
      float aqq = As[qi * 65 + qi];
      float apq = As[pi * 65 + qi];
      float cc = 1.f, ss = 0.f;
      if (apq * apq > skipthr) {
        float tau = (aqq - app) / (2.f * apq);
        float tt = copysignf(1.f, tau) / (fabsf(tau) + sqrtf(1.f + tau * tau));
        cc = rsqrtf(1.f + tt * tt);
        ss = tt * cc;
      }
      // block-uniform triviality (every warp computes the identical set)
      if (__all_sync(~0u, ss == 0.f)) continue;  // no writes -> no barriers needed
      __syncthreads();  // rotation reads done before block writes

      // phase b: fused two-sided update. Thread (wid,lane) owns A blocks
      // (i=lane, j=wid+4k, k<8) and V col-pairs j at rows lane, lane+32.
#pragma unroll
      for (int k = 0; k < 8; k++) {
        const int j = wid + 4 * k;
        const float cj = __shfl_sync(~0u, cc, j);
        const float sj = __shfl_sync(~0u, ss, j);
        const int tj = (sj == 0.f);                  // warp-uniform
        const int pj = ((j >> h) << (h + 1)) | (j & msk);
        const int qj = pj ^ mr;

        float b00 = As[pi * 65 + pj], b01 = As[pi * 65 + qj];
        float b10 = As[qi * 65 + pj], b11 = As[qi * 65 + qj];
        float t00 = cc * b00 - ss * b10, t01 = cc * b01 - ss * b11;
        float t10 = ss * b00 + cc * b10, t11 = ss * b01 + cc * b11;
        As[pi * 65 + pj] = t00 * cj - t01 * sj;
        As[pi * 65 + qj] = t00 * sj + t01 * cj;
        As[qi * 65 + pj] = t10 * cj - t11 * sj;
        As[qi * 65 + qj] = t10 * sj + t11 * cj;

        if (!tj) {
          float vp0 = Vs[lane * 65 + pj], vq0 = Vs[lane * 65 + qj];
          Vs[lane * 65 + pj] = cj * vp0 - sj * vq0;
          Vs[lane * 65 + qj] = sj * vp0 + cj * vq0;
          float vp1 = Vs[(lane + 32) * 65 + pj], vq1 = Vs[(lane + 32) * 65 + qj];
          Vs[(lane + 32) * 65 + pj] = cj * vp1 - sj * vq1;
          Vs[(lane + 32) * 65 + qj] = sj * vp1 + cj * vq1;
        }
      }
      __syncthreads();
    }
  }
  if (t < 64) g_w[(size_t)m * 64 + t] = As[t * 65 + t];
  for (int i = t; i < 4096; i += 128)
    g_Vt[(size_t)m * 4096 + i] = Vs[(i >> 6) * 65 + (i & 63)];
}

// ---------------- reconstructions V f(w) V^T --------------------------------
__global__ void k_recon_pre() {  // state = V clip(w) V^T ; Lstate = V log(clip(w)) V^T
  __shared__ float Vs[4160], fc[64], fl[64];
  const int m = blockIdx.x, t = threadIdx.x;
  const int slot = m >> 9, bc = m & 511;
  const float* V = g_Vt + (size_t)m * 4096;
  for (int i = t; i < 4096; i += 256) Vs[(i >> 6) * 65 + (i & 63)] = V[i];
  if (t < 64) {
    float cw = fmaxf(g_w[(size_t)m * 64 + t], EPSV);
    fc[t] = cw; fl[t] = logf(cw);
  }
  __syncthreads();
  const int i0 = (t >> 4) * 4, j0 = (t & 15) * 4;
  float a[4][4] = {}, b[4][4] = {};
  for (int k = 0; k < 64; k++) {
    float u[4], v[4];
#pragma unroll
    for (int r = 0; r < 4; r++) u[r] = Vs[(i0 + r) * 65 + k];
#pragma unroll
    for (int c = 0; c < 4; c++) v[c] = Vs[(j0 + c) * 65 + k];
    float fck = fc[k], flk = fl[k];
#pragma unroll
    for (int r = 0; r < 4; r++)
#pragma unroll
      for (int c = 0; c < 4; c++) {
        float p = u[r] * v[c];
        a[r][c] += p * fck;
        b[r][c] += p * flk;
      }
  }
  float* st = g_state + (size_t)(slot * 512 + bc) * 4096;
  float* ls = g_Lstate + (size_t)(slot * 512 + bc) * 4096;
#pragma unroll
  for (int r = 0; r < 4; r++)
#pragma unroll
    for (int c = 0; c < 4; c++) {
      st[(i0 + r) * 64 + j0 + c] = a[r][c];
      ls[(i0 + r) * 64 + j0 + c] = b[r][c];
    }
}

__global__ void k_recon_log() {  // g_B[m] = V log(clip(w)) V^T
  __shared__ float Vs[4160], fl[64];
  const int m = blockIdx.x, t = threadIdx.x;
  const float* V = g_Vt + (size_t)m * 4096;
  for (int i = t; i < 4096; i += 256) Vs[(i >> 6) * 65 + (i & 63)] = V[i];
  if (t < 64) fl[t] = logf(fmaxf(g_w[(size_t)m * 64 + t], EPSV));
  __syncthreads();
  const int i0 = (t >> 4) * 4, j0 = (t & 15) * 4;
  float a[4][4] = {};
  for (int k = 0; k < 64; k++) {
    float u[4], v[4];
#pragma unroll
    for (int r = 0; r < 4; r++) u[r] = Vs[(i0 + r) * 65 + k];
#pragma unroll
    for (int c = 0; c < 4; c++) v[c] = Vs[(j0 + c) * 65 + k] * fl[k];
#pragma unroll
    for (int r = 0; r < 4; r++)
#pragma unroll
      for (int c = 0; c < 4; c++) a[r][c] += u[r] * v[c];
  }
  float* dst = g_B + (size_t)m * 4096;
#pragma unroll
  for (int r = 0; r < 4; r++)
#pragma unroll
    for (int c = 0; c < 4; c++) dst[(i0 + r) * 64 + j0 + c] = a[r][c];
}

__global__ void k_recon_exp(int ns, float* __restrict__ out) {  // state = V exp(w) V^T
  __shared__ float Vs[4160], fe[64];
  const int m = blockIdx.x, t = threadIdx.x;
  const float* V = g_Vt + (size_t)m * 4096;
  for (int i = t; i < 4096; i += 256) Vs[(i >> 6) * 65 + (i & 63)] = V[i];
  if (t < 64) fe[t] = expf(g_w[(size_t)m * 64 + t]);
  __syncthreads();
  const int i0 = (t >> 4) * 4, j0 = (t & 15) * 4;
  float a[4][4] = {};
  for (int k = 0; k < 64; k++) {
    float u[4], v[4];
#pragma unroll
    for (int r = 0; r < 4; r++) u[r] = Vs[(i0 + r) * 65 + k];
#pragma unroll
    for (int c = 0; c < 4; c++) v[c] = Vs[(j0 + c) * 65 + k] * fe[k];
#pragma unroll
    for (int r = 0; r < 4; r++)
#pragma unroll
      for (int c = 0; c < 4; c++) a[r][c] += u[r] * v[c];
  }
  float* st = g_state + (size_t)(ns * 512 + m) * 4096;
  int b = m >> 4, c0 = m & 15;
  float* od = out + (size_t)((b * 48 + (ns - 2) * 16 + c0)) * 4096;
#pragma unroll
  for (int r = 0; r < 4; r++)
#pragma unroll
    for (int c = 0; c < 4; c++) {
      float v = a[r][c];
      st[(i0 + r) * 64 + j0 + c] = v;
      od[(i0 + r) * 64 + j0 + c] = v;
    }
}

// ---------------- mean of weighted logs --------------------------------------
__global__ void k_mean(const float* __restrict__ wts, int o, int J, int ns) {
  const int bc = blockIdx.x, t = threadIdx.x;
  float wl[4][4];
  for (int j = 0; j < J; j++)
    for (int k = 0; k < 4; k++) wl[j][k] = wts[(o + j) * 4 + k];
  const float inv = 1.f / (float)J;
  float* dst = g_Lstate + (size_t)(ns * 512 + bc) * 4096;
  for (int e = t; e < 4096; e += 256) {
    float acc = 0.f;
    for (int j = 0; j < J; j++) {
      acc += wl[j][0] * g_Lstate[(size_t)(j * 512 + bc) * 4096 + e];
      for (int r = 0; r < 3; r++)
        acc += wl[j][r + 1] * g_B[(size_t)((j * 3 + r) * 512 + bc) * 4096 + e];
    }
    dst[e] = acc * inv;
  }
}

// ---------------- host ---------------------------------------------------------
extern "C" void kernel_launch(void* const* d_in, const int* in_sizes, int n_in,
                              void* d_out, int out_size) {
  const float* s0  = (const float*)d_in[0];
  const float* s1  = (const float*)d_in[1];
  const float* wts = (const float*)d_in[2];
  const float* Wp0 = (const float*)d_in[3];
  const float* Wp1 = (const float*)d_in[4];
  const float* Wop = (const float*)d_in[5];
  float* out = (float*)d_out;
  (void)in_sizes; (void)n_in; (void)out_size;

  // preprocess: reig(bimap(s_i, Wp_i)) + cached log
  k_bimap_pre<<<1024, 256>>>(s0, s1, Wp0, Wp1);
  k_eigh<<<1024, 128>>>(0, 0);
  k_recon_pre<<<1024, 256>>>();

  const int offs[3] = {0, 2, 5};
  for (int s = 0; s < 3; s++) {
    int J = 2 + s, o = offs[s], ns = 2 + s;
    int nb = J * 3 * 512;
    k_bimap_step<<<nb, 256>>>(Wop, o);
    k_eigh<<<nb, 128>>>(0, 0);
    k_recon_log<<<nb, 256>>>();
    k_mean<<<512, 256>>>(wts, o, J, ns);
    k_eigh<<<512, 128>>>(1, ns * 512);
    k_recon_exp<<<512, 256>>>(ns, out);
  }
}